// round 1
// baseline (speedup 1.0000x reference)
#include <cuda_runtime.h>
#include <cstdint>

#define IN_F  4096
#define OUT_F 16384
#define NB    8      // batch vectors
#define RPW   8      // rows per warp
#define WARPS 4
#define THREADS (WARPS * 32)
#define ROWS_PER_CTA (RPW * WARPS)   // 32
#define NCHUNK (IN_F / 128)          // 32 j-iterations (each lane: 4 cols per j)

__constant__ float NF4_CODE[16] = {
    -1.0f, -0.6961928009986877f, -0.5250730514526367f, -0.39491748809814453f,
    -0.28444138169288635f, -0.18477343022823334f, -0.09105003625154495f, 0.0f,
    0.07958029955625534f, 0.16093020141124725f, 0.24611230194568634f,
    0.33791524171829224f, 0.44070982933044434f, 0.5626170039176941f,
    0.7229568362236023f, 1.0f};

// ---- packed f32x2 helpers (Blackwell FFMA2 path: only reachable via PTX) ----
__device__ __forceinline__ unsigned long long pk2(float lo, float hi) {
    unsigned long long r;
    asm("mov.b64 %0, {%1, %2};" : "=l"(r)
        : "r"(__float_as_uint(lo)), "r"(__float_as_uint(hi)));
    return r;
}
__device__ __forceinline__ void upk2(unsigned long long v, float& lo, float& hi) {
    unsigned int a, b;
    asm("mov.b64 {%0, %1}, %2;" : "=r"(a), "=r"(b) : "l"(v));
    lo = __uint_as_float(a); hi = __uint_as_float(b);
}
__device__ __forceinline__ void fma2(unsigned long long& acc,
                                     unsigned long long a, unsigned long long b) {
    asm("fma.rn.f32x2 %0, %1, %2, %0;" : "+l"(acc) : "l"(a), "l"(b));
}
__device__ __forceinline__ unsigned long long mul2(unsigned long long a,
                                                   unsigned long long b) {
    unsigned long long r;
    asm("mul.rn.f32x2 %0, %1, %2;" : "=l"(r) : "l"(a), "l"(b));
    return r;
}

__global__ __launch_bounds__(THREADS, 2)
void nf4_qlinear_kernel(const float* __restrict__ x,
                        const int*   __restrict__ codes,
                        const float* __restrict__ absmax,
                        float*       __restrict__ out) {
    // NF4 table replicated per lane: tab[c*32 + lane] -> bank == lane, conflict-free
    __shared__ float tab[16 * 32];
    const int tid  = threadIdx.x;
    const int lane = tid & 31;
    const int warp = tid >> 5;
    #pragma unroll
    for (int i = tid; i < 16 * 32; i += THREADS) tab[i] = NF4_CODE[i >> 5];
    __syncthreads();

    const int row0 = blockIdx.x * ROWS_PER_CTA + warp * RPW;

    // acc[r][b] packs (even-col partial, odd-col partial)
    unsigned long long acc[RPW][NB];
    #pragma unroll
    for (int r = 0; r < RPW; ++r)
        #pragma unroll
        for (int b = 0; b < NB; ++b) acc[r][b] = 0ULL;

    const float sel = 0.0f; (void)sel;

    for (int j = 0; j < NCHUNK; ++j) {
        const int col = j * 128 + lane * 4;

        // Stream codes for all RPW rows first -> 8 independent LDG.128 in flight
        int4 cv[RPW];
        #pragma unroll
        for (int r = 0; r < RPW; ++r) {
            const size_t off = (size_t)(row0 + r) * IN_F + col;
            cv[r] = __ldcs(reinterpret_cast<const int4*>(codes + off));
        }

        // x pairs for this lane's 4 columns, all 8 batches (L1-resident, .ca)
        unsigned long long x01[NB], x23[NB];
        #pragma unroll
        for (int b = 0; b < NB; ++b) {
            const float4 xv =
                *reinterpret_cast<const float4*>(x + b * IN_F + col);
            x01[b] = pk2(xv.x, xv.y);
            x23[b] = pk2(xv.z, xv.w);
        }

        #pragma unroll
        for (int r = 0; r < RPW; ++r) {
            // this lane's 4 cols are inside block (2j + (lane>=16))
            const float2 amp = *reinterpret_cast<const float2*>(
                absmax + (size_t)(row0 + r) * (IN_F / 64) + j * 2);
            const float a = (lane < 16) ? amp.x : amp.y;
            const unsigned long long a2 = pk2(a, a);

            const unsigned long long t01 =
                pk2(tab[(cv[r].x << 5) + lane], tab[(cv[r].y << 5) + lane]);
            const unsigned long long t23 =
                pk2(tab[(cv[r].z << 5) + lane], tab[(cv[r].w << 5) + lane]);
            const unsigned long long w01 = mul2(t01, a2);
            const unsigned long long w23 = mul2(t23, a2);

            #pragma unroll
            for (int b = 0; b < NB; ++b) {
                fma2(acc[r][b], w01, x01[b]);
                fma2(acc[r][b], w23, x23[b]);
            }
        }
    }

    // Reduce pairs, then warp-reduce, store out[b, row]
    #pragma unroll
    for (int r = 0; r < RPW; ++r) {
        #pragma unroll
        for (int b = 0; b < NB; ++b) {
            float lo, hi;
            upk2(acc[r][b], lo, hi);
            float s = lo + hi;
            #pragma unroll
            for (int off = 16; off > 0; off >>= 1)
                s += __shfl_xor_sync(0xffffffffu, s, off);
            if (lane == 0) out[(size_t)b * OUT_F + row0 + r] = s;
        }
    }
}

extern "C" void kernel_launch(void* const* d_in, const int* in_sizes, int n_in,
                              void* d_out, int out_size) {
    const float* x      = (const float*)d_in[0];   // [8,1,4096] f32
    const int*   codes  = (const int*)d_in[1];     // [16384,4096] i32 (0..15)
    const float* absmax = (const float*)d_in[2];   // [16384,64] f32
    float*       out    = (float*)d_out;           // [8,1,16384] f32

    (void)in_sizes; (void)n_in; (void)out_size;
    nf4_qlinear_kernel<<<OUT_F / ROWS_PER_CTA, THREADS>>>(x, codes, absmax, out);
}

// round 2
// speedup vs baseline: 1.0332x; 1.0332x over previous
#include <cuda_runtime.h>
#include <cstdint>

#define IN_F  4096
#define OUT_F 16384
#define NB    8      // batch vectors
#define RPW   4      // rows per warp
#define WARPS 8
#define THREADS (WARPS * 32)          // 256
#define ROWS_PER_CTA (RPW * WARPS)    // 32
#define NCHUNK (IN_F / 128)           // 32 j-iterations (each lane: 4 cols per j)

__constant__ float NF4_CODE[16] = {
    -1.0f, -0.6961928009986877f, -0.5250730514526367f, -0.39491748809814453f,
    -0.28444138169288635f, -0.18477343022823334f, -0.09105003625154495f, 0.0f,
    0.07958029955625534f, 0.16093020141124725f, 0.24611230194568634f,
    0.33791524171829224f, 0.44070982933044434f, 0.5626170039176941f,
    0.7229568362236023f, 1.0f};

// ---- packed f32x2 helpers (Blackwell FFMA2 path: only reachable via PTX) ----
__device__ __forceinline__ unsigned long long pk2(float lo, float hi) {
    unsigned long long r;
    asm("mov.b64 %0, {%1, %2};" : "=l"(r)
        : "r"(__float_as_uint(lo)), "r"(__float_as_uint(hi)));
    return r;
}
__device__ __forceinline__ void upk2(unsigned long long v, float& lo, float& hi) {
    unsigned int a, b;
    asm("mov.b64 {%0, %1}, %2;" : "=r"(a), "=r"(b) : "l"(v));
    lo = __uint_as_float(a); hi = __uint_as_float(b);
}
__device__ __forceinline__ void fma2(unsigned long long& acc,
                                     unsigned long long a, unsigned long long b) {
    asm("fma.rn.f32x2 %0, %1, %2, %0;" : "+l"(acc) : "l"(a), "l"(b));
}
__device__ __forceinline__ unsigned long long mul2(unsigned long long a,
                                                   unsigned long long b) {
    unsigned long long r;
    asm("mul.rn.f32x2 %0, %1, %2;" : "=l"(r) : "l"(a), "l"(b));
    return r;
}

__global__ __launch_bounds__(THREADS, 2)
void nf4_qlinear_kernel(const float* __restrict__ x,
                        const int*   __restrict__ codes,
                        const float* __restrict__ absmax,
                        float*       __restrict__ out) {
    // NF4 table replicated per lane: tab[c*32 + lane] -> bank == lane, conflict-free
    __shared__ float tab[16 * 32];
    const int tid  = threadIdx.x;
    const int lane = tid & 31;
    const int warp = tid >> 5;
    #pragma unroll
    for (int i = tid; i < 16 * 32; i += THREADS) tab[i] = NF4_CODE[i >> 5];
    __syncthreads();

    const int row0 = blockIdx.x * ROWS_PER_CTA + warp * RPW;

    // acc[r][b] packs (even-col partial, odd-col partial)
    unsigned long long acc[RPW][NB];
    #pragma unroll
    for (int r = 0; r < RPW; ++r)
        #pragma unroll
        for (int b = 0; b < NB; ++b) acc[r][b] = 0ULL;

    for (int j = 0; j < NCHUNK; ++j) {
        const int col = j * 128 + lane * 4;

        // Stream codes for RPW rows first -> independent LDG.128 in flight
        int4 cv[RPW];
        #pragma unroll
        for (int r = 0; r < RPW; ++r) {
            const size_t off = (size_t)(row0 + r) * IN_F + col;
            cv[r] = __ldcs(reinterpret_cast<const int4*>(codes + off));
        }

        // Dequantize this chunk's 4 columns for all RPW rows -> packed weights
        unsigned long long w01[RPW], w23[RPW];
        #pragma unroll
        for (int r = 0; r < RPW; ++r) {
            // this lane's 4 cols are inside block (2j + (lane>=16))
            const float2 amp = *reinterpret_cast<const float2*>(
                absmax + (size_t)(row0 + r) * (IN_F / 64) + j * 2);
            const float a = (lane < 16) ? amp.x : amp.y;
            const unsigned long long a2 = pk2(a, a);
            const unsigned long long t01 =
                pk2(tab[(cv[r].x << 5) + lane], tab[(cv[r].y << 5) + lane]);
            const unsigned long long t23 =
                pk2(tab[(cv[r].z << 5) + lane], tab[(cv[r].w << 5) + lane]);
            w01[r] = mul2(t01, a2);
            w23[r] = mul2(t23, a2);
        }

        // x loaded just-in-time per batch (L1-resident), FMA into all rows
        #pragma unroll
        for (int b = 0; b < NB; ++b) {
            const float4 xv =
                *reinterpret_cast<const float4*>(x + b * IN_F + col);
            const unsigned long long x01 = pk2(xv.x, xv.y);
            const unsigned long long x23 = pk2(xv.z, xv.w);
            #pragma unroll
            for (int r = 0; r < RPW; ++r) {
                fma2(acc[r][b], w01[r], x01);
                fma2(acc[r][b], w23[r], x23);
            }
        }
    }

    // Reduce pairs, then warp-reduce, store out[b, row]
    #pragma unroll
    for (int r = 0; r < RPW; ++r) {
        #pragma unroll
        for (int b = 0; b < NB; ++b) {
            float lo, hi;
            upk2(acc[r][b], lo, hi);
            float s = lo + hi;
            #pragma unroll
            for (int off = 16; off > 0; off >>= 1)
                s += __shfl_xor_sync(0xffffffffu, s, off);
            if (lane == 0) out[(size_t)b * OUT_F + row0 + r] = s;
        }
    }
}

extern "C" void kernel_launch(void* const* d_in, const int* in_sizes, int n_in,
                              void* d_out, int out_size) {
    const float* x      = (const float*)d_in[0];   // [8,1,4096] f32
    const int*   codes  = (const int*)d_in[1];     // [16384,4096] i32 (0..15)
    const float* absmax = (const float*)d_in[2];   // [16384,64] f32
    float*       out    = (float*)d_out;           // [8,1,16384] f32

    (void)in_sizes; (void)n_in; (void)out_size;
    nf4_qlinear_kernel<<<OUT_F / ROWS_PER_CTA, THREADS>>>(x, codes, absmax, out);
}